// round 1
// baseline (speedup 1.0000x reference)
#include <cuda_runtime.h>
#include <math.h>

// Problem caps (from reference): N=50000 nodes, E=800000 edges, D=64.
#define MAXN 50000
#define MAXE 800000

// Scratch (device globals — no allocation allowed in kernel_launch).
__device__ float g_tmp[MAXN * 64];    // h @ W
__device__ float g_h[MAXN * 64];      // layer activations (input to next layer)
__device__ float g_dinv[MAXN];        // 1/sqrt(deg+1)
__device__ int   g_deg[MAXN];
__device__ int   g_cursor[MAXN];
__device__ int   g_rowptr[MAXN + 1];
__device__ int   g_col[MAXE];         // CSR by dst: src indices

// ---------------------------------------------------------------------------
// CSR build
// ---------------------------------------------------------------------------
__global__ void k_init(int n) {
    int i = blockIdx.x * blockDim.x + threadIdx.x;
    if (i < n) { g_deg[i] = 0; g_cursor[i] = 0; }
}

__global__ void k_count(const int* __restrict__ dst, int e) {
    int i = blockIdx.x * blockDim.x + threadIdx.x;
    if (i < e) atomicAdd(&g_deg[dst[i]], 1);
}

__global__ void k_dinv(int n) {
    int i = blockIdx.x * blockDim.x + threadIdx.x;
    if (i < n) g_dinv[i] = rsqrtf((float)(g_deg[i] + 1));  // +1 self-loop
}

// Single-block exclusive prefix sum over g_deg -> g_rowptr
__global__ void k_scan(int n) {
    __shared__ int sh[1024];
    int tid = threadIdx.x;
    int chunk = (n + 1023) >> 10;
    int start = tid * chunk;
    int s = 0;
    for (int j = 0; j < chunk; ++j) {
        int idx = start + j;
        if (idx < n) s += g_deg[idx];
    }
    sh[tid] = s;
    __syncthreads();
    for (int off = 1; off < 1024; off <<= 1) {
        int add = (tid >= off) ? sh[tid - off] : 0;
        __syncthreads();
        sh[tid] += add;
        __syncthreads();
    }
    int run = sh[tid] - s;  // exclusive prefix of this thread's chunk
    for (int j = 0; j < chunk; ++j) {
        int idx = start + j;
        if (idx < n) { g_rowptr[idx] = run; run += g_deg[idx]; }
    }
    if (tid == 1023) g_rowptr[n] = sh[1023];
}

__global__ void k_fill(const int* __restrict__ src, const int* __restrict__ dst, int e) {
    int i = blockIdx.x * blockDim.x + threadIdx.x;
    if (i < e) {
        int d = dst[i];
        int pos = g_rowptr[d] + atomicAdd(&g_cursor[d], 1);
        g_col[pos] = src[i];
    }
}

// ---------------------------------------------------------------------------
// GEMM: C[n,64] = A[n,64] @ W[64,64]   (no bias; bias folded into aggregation)
// Block: 256 threads, tile 128 rows x 64 cols, micro-tile 8x4 per thread.
// ---------------------------------------------------------------------------
__global__ void k_gemm(const float* __restrict__ Aext, int useExt,
                       const float* __restrict__ W, int n) {
    __shared__ float As[128][64];   // 32 KB
    __shared__ float Ws[64][64];    // 16 KB
    const float* A = useExt ? Aext : g_h;
    int tid = threadIdx.x;
    int block_row = blockIdx.x * 128;

    // Load W (4096 floats, float4)
    {
        const float4* w4 = (const float4*)W;
        float4* ws4 = (float4*)&Ws[0][0];
#pragma unroll
        for (int j = 0; j < 4; ++j) ws4[tid + 256 * j] = w4[tid + 256 * j];
    }
    // Load A tile (8192 floats, float4, coalesced)
    {
#pragma unroll
        for (int j = 0; j < 8; ++j) {
            int idx = tid + 256 * j;          // float4 index in tile
            int r = idx >> 4, k4 = idx & 15;  // 16 float4 per row
            int gr = block_row + r;
            float4 v = make_float4(0.f, 0.f, 0.f, 0.f);
            if (gr < n) v = ((const float4*)A)[gr * 16 + k4];
            ((float4*)&As[r][0])[k4] = v;
        }
    }
    __syncthreads();

    int tr = tid >> 4;   // 0..15 -> rows tr*8 .. tr*8+7
    int tc = tid & 15;   // 0..15 -> cols tc*4 .. tc*4+3
    float acc[8][4];
#pragma unroll
    for (int j = 0; j < 8; ++j)
#pragma unroll
        for (int c = 0; c < 4; ++c) acc[j][c] = 0.f;

#pragma unroll 4
    for (int k = 0; k < 64; ++k) {
        float4 b4 = ((const float4*)&Ws[k][0])[tc];
#pragma unroll
        for (int j = 0; j < 8; ++j) {
            float a = As[tr * 8 + j][k];
            acc[j][0] = fmaf(a, b4.x, acc[j][0]);
            acc[j][1] = fmaf(a, b4.y, acc[j][1]);
            acc[j][2] = fmaf(a, b4.z, acc[j][2]);
            acc[j][3] = fmaf(a, b4.w, acc[j][3]);
        }
    }

#pragma unroll
    for (int j = 0; j < 8; ++j) {
        int gr = block_row + tr * 8 + j;
        if (gr < n) {
            float4 v = make_float4(acc[j][0], acc[j][1], acc[j][2], acc[j][3]);
            ((float4*)&g_tmp[gr * 64])[tc] = v;
        }
    }
}

// ---------------------------------------------------------------------------
// Aggregation + bias + ELU. Warp per node, float2 per lane (64 features).
// out = ELU( dinv[i]*(sum_s dinv[s]*tmp[s]) + dinv[i]^2*tmp[i] + b )
// Writes g_h (next layer input) and d_out slice (pitch 192).
// ---------------------------------------------------------------------------
__global__ void k_agg(const float* __restrict__ bias,
                      float* __restrict__ out, int col_off, int n) {
    int w = (blockIdx.x * blockDim.x + threadIdx.x) >> 5;
    int lane = threadIdx.x & 31;
    if (w >= n) return;
    float di = g_dinv[w];
    int beg = g_rowptr[w];
    int end = g_rowptr[w + 1];
    const float2* t2 = (const float2*)g_tmp;

    float ax = 0.f, ay = 0.f;
    int p = beg;
    // unroll-by-4 for memory-level parallelism on the random L2 gathers
    for (; p + 3 < end; p += 4) {
        int s0 = g_col[p], s1 = g_col[p + 1], s2 = g_col[p + 2], s3 = g_col[p + 3];
        float d0 = g_dinv[s0], d1 = g_dinv[s1], d2 = g_dinv[s2], d3 = g_dinv[s3];
        float2 v0 = t2[s0 * 32 + lane];
        float2 v1 = t2[s1 * 32 + lane];
        float2 v2 = t2[s2 * 32 + lane];
        float2 v3 = t2[s3 * 32 + lane];
        ax = fmaf(d0, v0.x, ax); ay = fmaf(d0, v0.y, ay);
        ax = fmaf(d1, v1.x, ax); ay = fmaf(d1, v1.y, ay);
        ax = fmaf(d2, v2.x, ax); ay = fmaf(d2, v2.y, ay);
        ax = fmaf(d3, v3.x, ax); ay = fmaf(d3, v3.y, ay);
    }
    for (; p < end; ++p) {
        int s = g_col[p];
        float ds = g_dinv[s];
        float2 v = t2[s * 32 + lane];
        ax = fmaf(ds, v.x, ax);
        ay = fmaf(ds, v.y, ay);
    }
    // self-loop + symmetric norm
    float2 vs = t2[w * 32 + lane];
    ax = di * (ax + di * vs.x);
    ay = di * (ay + di * vs.y);
    float2 bb = ((const float2*)bias)[lane];
    ax += bb.x; ay += bb.y;
    // ELU (alpha=1)
    ax = ax > 0.f ? ax : expm1f(ax);
    ay = ay > 0.f ? ay : expm1f(ay);

    ((float2*)g_h)[w * 32 + lane] = make_float2(ax, ay);
    float* orow = out + (size_t)w * 192 + col_off;
    ((float2*)orow)[lane] = make_float2(ax, ay);
}

// ---------------------------------------------------------------------------
extern "C" void kernel_launch(void* const* d_in, const int* in_sizes, int n_in,
                              void* d_out, int out_size) {
    const float* x  = (const float*)d_in[0];
    const int*   ei = (const int*)d_in[1];
    const float* W[3] = { (const float*)d_in[2], (const float*)d_in[4], (const float*)d_in[6] };
    const float* B[3] = { (const float*)d_in[3], (const float*)d_in[5], (const float*)d_in[7] };
    int n = in_sizes[0] / 64;
    int e = in_sizes[1] / 2;
    const int* src = ei;
    const int* dst = ei + e;
    float* out = (float*)d_out;

    int nb_n = (n + 255) / 256;
    int nb_e = (e + 255) / 256;

    k_init<<<nb_n, 256>>>(n);
    k_count<<<nb_e, 256>>>(dst, e);
    k_dinv<<<nb_n, 256>>>(n);
    k_scan<<<1, 1024>>>(n);
    k_fill<<<nb_e, 256>>>(src, dst, e);

    int gemm_blocks = (n + 127) / 128;
    int agg_blocks = (n + 7) / 8;   // 8 warps (nodes) per 256-thread block
    for (int l = 0; l < 3; ++l) {
        k_gemm<<<gemm_blocks, 256>>>(x, l == 0 ? 1 : 0, W[l], n);
        k_agg<<<agg_blocks, 256>>>(B[l], out, l * 64, n);
    }
}

// round 2
// speedup vs baseline: 1.3291x; 1.3291x over previous
#include <cuda_runtime.h>
#include <math.h>

// Problem caps (from reference): N=50000 nodes, E=800000 edges, D=64.
#define MAXN 50000
#define MAXE 800000
#define SCAN_B 256
#define MAXBLK ((MAXN + SCAN_B - 1) / SCAN_B)   // 196

// Scratch (device globals — no allocation allowed in kernel_launch).
__device__ float g_tmp[MAXN * 64];    // h @ W
__device__ float g_h[MAXN * 64];      // layer activations (input to next layer)
__device__ float g_dinv[MAXN];        // 1/sqrt(deg+1)
__device__ int   g_deg[MAXN];
__device__ int   g_cursor[MAXN];
__device__ int   g_rowptr[MAXN + 1];
__device__ int   g_col[MAXE];         // CSR by dst: src indices
__device__ int   g_bsum[MAXBLK];      // per-block totals
__device__ int   g_boff[MAXBLK];      // exclusive offsets of block totals

// ---------------------------------------------------------------------------
// CSR build
// ---------------------------------------------------------------------------
__global__ void k_init(int n) {
    int i = blockIdx.x * blockDim.x + threadIdx.x;
    if (i < n) { g_deg[i] = 0; g_cursor[i] = 0; }
}

__global__ void k_count(const int* __restrict__ dst, int e) {
    int i = blockIdx.x * blockDim.x + threadIdx.x;
    if (i < e) atomicAdd(&g_deg[dst[i]], 1);
}

// Stage A: per-256-tile exclusive scan of g_deg -> g_rowptr (local), tile total
// -> g_bsum. Also computes g_dinv (folded in, deg already in registers).
__global__ void k_scanA(int n) {
    int i = blockIdx.x * SCAN_B + threadIdx.x;
    int lane = threadIdx.x & 31, wid = threadIdx.x >> 5;
    int v = (i < n) ? g_deg[i] : 0;
    if (i < n) g_dinv[i] = rsqrtf((float)(v + 1));   // +1 self-loop

    // warp inclusive scan
    int x = v;
#pragma unroll
    for (int o = 1; o < 32; o <<= 1) {
        int t = __shfl_up_sync(0xffffffffu, x, o);
        if (lane >= o) x += t;
    }
    __shared__ int wsum[8];
    if (lane == 31) wsum[wid] = x;
    __syncthreads();
    if (wid == 0) {
        int s = (lane < 8) ? wsum[lane] : 0;
#pragma unroll
        for (int o = 1; o < 8; o <<= 1) {
            int t = __shfl_up_sync(0xffffffffu, s, o);
            if (lane >= o) s += t;
        }
        if (lane < 8) wsum[lane] = s;
    }
    __syncthreads();
    int excl = x - v + (wid ? wsum[wid - 1] : 0);
    if (i < n) g_rowptr[i] = excl;
    if (threadIdx.x == SCAN_B - 1) g_bsum[blockIdx.x] = wsum[7];
}

// Stage B: scan the (<=256) block totals. One block.
__global__ void k_scanB(int nb, int n) {
    int tid = threadIdx.x;
    int lane = tid & 31, wid = tid >> 5;
    int v = (tid < nb) ? g_bsum[tid] : 0;
    int x = v;
#pragma unroll
    for (int o = 1; o < 32; o <<= 1) {
        int t = __shfl_up_sync(0xffffffffu, x, o);
        if (lane >= o) x += t;
    }
    __shared__ int wsum[8];
    if (lane == 31) wsum[wid] = x;
    __syncthreads();
    if (wid == 0) {
        int s = (lane < 8) ? wsum[lane] : 0;
#pragma unroll
        for (int o = 1; o < 8; o <<= 1) {
            int t = __shfl_up_sync(0xffffffffu, s, o);
            if (lane >= o) s += t;
        }
        if (lane < 8) wsum[lane] = s;
    }
    __syncthreads();
    int excl = x - v + (wid ? wsum[wid - 1] : 0);
    if (tid < nb) g_boff[tid] = excl;
    if (tid == SCAN_B - 1) g_rowptr[n] = wsum[7];   // grand total = E
}

// Stage C: add block offsets.
__global__ void k_scanC(int n) {
    int i = blockIdx.x * blockDim.x + threadIdx.x;
    if (i < n) g_rowptr[i] += g_boff[i >> 8];
}

__global__ void k_fill(const int* __restrict__ src, const int* __restrict__ dst, int e) {
    int i = blockIdx.x * blockDim.x + threadIdx.x;
    if (i < e) {
        int d = dst[i];
        int pos = g_rowptr[d] + atomicAdd(&g_cursor[d], 1);
        g_col[pos] = src[i];
    }
}

// ---------------------------------------------------------------------------
// GEMM: C[n,64] = A[n,64] @ W[64,64]   (no bias; bias folded into aggregation)
// Block: 256 threads, tile 128 rows x 64 cols, micro-tile 8x4 per thread.
// ---------------------------------------------------------------------------
__global__ void k_gemm(const float* __restrict__ Aext, int useExt,
                       const float* __restrict__ W, int n) {
    __shared__ float As[128][64];   // 32 KB
    __shared__ float Ws[64][64];    // 16 KB
    const float* A = useExt ? Aext : g_h;
    int tid = threadIdx.x;
    int block_row = blockIdx.x * 128;

    // Load W (4096 floats, float4)
    {
        const float4* w4 = (const float4*)W;
        float4* ws4 = (float4*)&Ws[0][0];
#pragma unroll
        for (int j = 0; j < 4; ++j) ws4[tid + 256 * j] = w4[tid + 256 * j];
    }
    // Load A tile (8192 floats, float4, coalesced)
    {
#pragma unroll
        for (int j = 0; j < 8; ++j) {
            int idx = tid + 256 * j;          // float4 index in tile
            int r = idx >> 4, k4 = idx & 15;  // 16 float4 per row
            int gr = block_row + r;
            float4 v = make_float4(0.f, 0.f, 0.f, 0.f);
            if (gr < n) v = ((const float4*)A)[gr * 16 + k4];
            ((float4*)&As[r][0])[k4] = v;
        }
    }
    __syncthreads();

    int tr = tid >> 4;   // 0..15 -> rows tr*8 .. tr*8+7
    int tc = tid & 15;   // 0..15 -> cols tc*4 .. tc*4+3
    float acc[8][4];
#pragma unroll
    for (int j = 0; j < 8; ++j)
#pragma unroll
        for (int c = 0; c < 4; ++c) acc[j][c] = 0.f;

#pragma unroll 4
    for (int k = 0; k < 64; ++k) {
        float4 b4 = ((const float4*)&Ws[k][0])[tc];
#pragma unroll
        for (int j = 0; j < 8; ++j) {
            float a = As[tr * 8 + j][k];
            acc[j][0] = fmaf(a, b4.x, acc[j][0]);
            acc[j][1] = fmaf(a, b4.y, acc[j][1]);
            acc[j][2] = fmaf(a, b4.z, acc[j][2]);
            acc[j][3] = fmaf(a, b4.w, acc[j][3]);
        }
    }

#pragma unroll
    for (int j = 0; j < 8; ++j) {
        int gr = block_row + tr * 8 + j;
        if (gr < n) {
            float4 v = make_float4(acc[j][0], acc[j][1], acc[j][2], acc[j][3]);
            ((float4*)&g_tmp[gr * 64])[tc] = v;
        }
    }
}

// ---------------------------------------------------------------------------
// Aggregation + bias + ELU. Warp per node, float2 per lane (64 features).
// out = ELU( dinv[i]*(sum_s dinv[s]*tmp[s]) + dinv[i]^2*tmp[i] + b )
// Writes g_h (next layer input) and d_out slice (pitch 192).
// ---------------------------------------------------------------------------
__global__ void k_agg(const float* __restrict__ bias,
                      float* __restrict__ out, int col_off, int n) {
    int w = (blockIdx.x * blockDim.x + threadIdx.x) >> 5;
    int lane = threadIdx.x & 31;
    if (w >= n) return;
    float di = g_dinv[w];
    int beg = g_rowptr[w];
    int end = g_rowptr[w + 1];
    const float2* t2 = (const float2*)g_tmp;

    float ax = 0.f, ay = 0.f;
    int p = beg;
    // unroll-by-4 for memory-level parallelism on the random L2 gathers
    for (; p + 3 < end; p += 4) {
        int s0 = g_col[p], s1 = g_col[p + 1], s2 = g_col[p + 2], s3 = g_col[p + 3];
        float d0 = g_dinv[s0], d1 = g_dinv[s1], d2 = g_dinv[s2], d3 = g_dinv[s3];
        float2 v0 = t2[s0 * 32 + lane];
        float2 v1 = t2[s1 * 32 + lane];
        float2 v2 = t2[s2 * 32 + lane];
        float2 v3 = t2[s3 * 32 + lane];
        ax = fmaf(d0, v0.x, ax); ay = fmaf(d0, v0.y, ay);
        ax = fmaf(d1, v1.x, ax); ay = fmaf(d1, v1.y, ay);
        ax = fmaf(d2, v2.x, ax); ay = fmaf(d2, v2.y, ay);
        ax = fmaf(d3, v3.x, ax); ay = fmaf(d3, v3.y, ay);
    }
    for (; p < end; ++p) {
        int s = g_col[p];
        float ds = g_dinv[s];
        float2 v = t2[s * 32 + lane];
        ax = fmaf(ds, v.x, ax);
        ay = fmaf(ds, v.y, ay);
    }
    // self-loop + symmetric norm
    float2 vs = t2[w * 32 + lane];
    ax = di * (ax + di * vs.x);
    ay = di * (ay + di * vs.y);
    float2 bb = ((const float2*)bias)[lane];
    ax += bb.x; ay += bb.y;
    // ELU (alpha=1)
    ax = ax > 0.f ? ax : expm1f(ax);
    ay = ay > 0.f ? ay : expm1f(ay);

    ((float2*)g_h)[w * 32 + lane] = make_float2(ax, ay);
    float* orow = out + (size_t)w * 192 + col_off;
    ((float2*)orow)[lane] = make_float2(ax, ay);
}

// ---------------------------------------------------------------------------
extern "C" void kernel_launch(void* const* d_in, const int* in_sizes, int n_in,
                              void* d_out, int out_size) {
    const float* x  = (const float*)d_in[0];
    const int*   ei = (const int*)d_in[1];
    const float* W[3] = { (const float*)d_in[2], (const float*)d_in[4], (const float*)d_in[6] };
    const float* B[3] = { (const float*)d_in[3], (const float*)d_in[5], (const float*)d_in[7] };
    int n = in_sizes[0] / 64;
    int e = in_sizes[1] / 2;
    const int* src = ei;
    const int* dst = ei + e;
    float* out = (float*)d_out;

    int nb_n = (n + 255) / 256;
    int nb_e = (e + 255) / 256;
    int nscan = (n + SCAN_B - 1) / SCAN_B;

    k_init<<<nb_n, 256>>>(n);
    k_count<<<nb_e, 256>>>(dst, e);
    k_scanA<<<nscan, SCAN_B>>>(n);
    k_scanB<<<1, SCAN_B>>>(nscan, n);
    k_scanC<<<nb_n, 256>>>(n);
    k_fill<<<nb_e, 256>>>(src, dst, e);

    int gemm_blocks = (n + 127) / 128;
    int agg_blocks = (n + 7) / 8;   // 8 warps (nodes) per 256-thread block
    for (int l = 0; l < 3; ++l) {
        k_gemm<<<gemm_blocks, 256>>>(x, l == 0 ? 1 : 0, W[l], n);
        k_agg<<<agg_blocks, 256>>>(B[l], out, l * 64, n);
    }
}